// round 16
// baseline (speedup 1.0000x reference)
// CrossLayerTranscoder — tf32 mma.sync GEMM. R16 = R15 champion (ldmatrix
// fragment loads, XOR swizzle, coalesced incremental cp.async loader) at
// 3 CTAs/SM: 2-stage pipeline with SINGLE barrier/iter (load(i+1) issued after
// sync into the slot compute(i-1) vacated; overlaps all of compute(i)).
// 64KB smem/CTA x3 = 192KB; launch_bounds(128,3) caps regs at 170.
//
// encode: feats[l] = relu(resid[l] @ enc_w[l]^T)            M=2048,N=512,K=2048
// decode: recon[t] = sum_{s<=t} feats[s] @ dec_w[s,t]^T     M=2048,N=2048,K=(t+1)*512

#include <cuda_runtime.h>
#include <cstdint>
#include <cstddef>

#define L_DIM 16
#define BS_DIM 2048
#define H_DIM 2048
#define F_DIM 512

#define TM 128
#define TN 128
#define TK 32
#define STAGES 2
#define NTHREADS 128

#define A_BYTES 16384                        // TM*TK*4
#define STAGE_BYTES 32768                    // A + B
#define SMEM_BYTES (STAGES * STAGE_BYTES)    // 64 KB (x3 CTAs = 192 KB)

__device__ __forceinline__ uint32_t smem_u32(const void* p) {
    uint32_t a;
    asm("{ .reg .u64 t; cvta.to.shared.u64 t, %1; cvt.u32.u64 %0, t; }" : "=r"(a) : "l"(p));
    return a;
}
__device__ __forceinline__ void cp_async16(uint32_t dst, const float* src) {
    asm volatile("cp.async.cg.shared.global [%0], [%1], 16;" :: "r"(dst), "l"(src));
}
__device__ __forceinline__ void cp_commit() { asm volatile("cp.async.commit_group;"); }
template <int N> __device__ __forceinline__ void cp_wait() {
    asm volatile("cp.async.wait_group %0;" :: "n"(N));
}
__device__ __forceinline__ void ldsm4(uint32_t* r, uint32_t addr) {
    asm volatile("ldmatrix.sync.aligned.m8n8.x4.shared.b16 {%0,%1,%2,%3}, [%4];"
                 : "=r"(r[0]), "=r"(r[1]), "=r"(r[2]), "=r"(r[3]) : "r"(addr));
}
__device__ __forceinline__ uint32_t cvt_tf32(uint32_t x) {
    uint32_t r; float f = __uint_as_float(x);
    asm("cvt.rna.tf32.f32 %0, %1;" : "=r"(r) : "f"(f));
    return r;
}
__device__ __forceinline__ void mma_tf32(float* c, const uint32_t* a, const uint32_t* b) {
    asm volatile(
        "mma.sync.aligned.m16n8k8.row.col.f32.tf32.tf32.f32 "
        "{%0,%1,%2,%3}, {%4,%5,%6,%7}, {%8,%9}, {%0,%1,%2,%3};"
        : "+f"(c[0]), "+f"(c[1]), "+f"(c[2]), "+f"(c[3])
        : "r"(a[0]), "r"(a[1]), "r"(a[2]), "r"(a[3]), "r"(b[0]), "r"(b[1]));
}

// SMEM tile layout (XOR swizzle): addr(row,k) = row*128 + ((k>>2 ^ (row&7))<<4)
// + (k&3)*4. ldmatrix bases fold the lane's k-group; ks XORs in as base^(ks<<5).

template <bool ENCODE>
__global__ __launch_bounds__(NTHREADS, 3)
void clt_gemm(const float* __restrict__ gA, const float* __restrict__ gB,
              float* __restrict__ gOut) {
    extern __shared__ float smem[];
    const uint32_t sbase = smem_u32(smem);
    const int tid  = threadIdx.x;
    const int lane = tid & 31;
    const int w    = tid >> 5;
    const int wm   = w & 1;        // 2 warps along M (64 rows)
    const int wn   = w >> 1;       // 2 warps along N (64 cols)
    const int r8   = lane >> 2;
    const int t    = lane & 3;
    const int m0   = blockIdx.x * TM;
    const int n0   = blockIdx.y * TN;
    const int z    = (int)gridDim.z - 1 - (int)blockIdx.z;   // heavy z first
    const int iters = ENCODE ? (H_DIM / TK) : ((z + 1) * (F_DIM / TK));
    const int LD   = ENCODE ? H_DIM : F_DIM;   // compile-time row pitch

    float acc[4][8][4];
    #pragma unroll
    for (int mt = 0; mt < 4; mt++)
        #pragma unroll
        for (int nt = 0; nt < 8; nt++)
            #pragma unroll
            for (int r = 0; r < 4; r++) acc[mt][nt][r] = 0.0f;

    // ---------- producer (coalesced, incremental) ----------
    const int tid8 = tid >> 3;
    const int cch  = tid & 7;
    const float* pA;
    const float* pB;
    if (ENCODE) {
        pA = gA + ((size_t)z * BS_DIM + m0 + tid8) * H_DIM + cch * 4;
        pB = gB + ((size_t)z * F_DIM + n0 + tid8) * H_DIM + cch * 4;
    } else {
        pA = gA + (size_t)(m0 + tid8) * F_DIM + cch * 4;               // feats[0]
        pB = gB + ((size_t)z * H_DIM + n0 + tid8) * F_DIM + cch * 4;   // dec_w[0][z]
    }
    const uint32_t dst0 = (uint32_t)tid8 * 128 + ((uint32_t)(cch ^ (tid8 & 7)) << 4);
    int fi = 0;
    auto load_stage = [&]() {
        const int slot = fi & 1;
        uint32_t dA = sbase + (uint32_t)slot * STAGE_BYTES + dst0;
        uint32_t dB = dA + A_BYTES;
        #pragma unroll
        for (int j = 0; j < 8; j++)
            cp_async16(dA + (uint32_t)j * 2048, pA + (size_t)j * 16 * LD);
        #pragma unroll
        for (int j = 0; j < 8; j++)
            cp_async16(dB + (uint32_t)j * 2048, pB + (size_t)j * 16 * LD);
        cp_commit();
        if (ENCODE) { pA += TK; pB += TK; }
        else {
            bool roll = (fi & 15) == 15;   // advance source layer s
            pA += roll ? ((size_t)BS_DIM * F_DIM - 15 * TK) : TK;
            pB += roll ? ((size_t)L_DIM * H_DIM * F_DIM - 15 * TK) : TK;
        }
        fi++;
    };

    // ---------- per-lane ldmatrix base offsets (bytes within tile) ----------
    uint32_t lbA[4], lbB[4];
    {
        const int rlA = lane & 15;
        const uint32_t glA = (uint32_t)(lane >> 4);
        #pragma unroll
        for (int mt = 0; mt < 4; mt++) {
            int row = wm * 64 + mt * 16 + rlA;
            lbA[mt] = (uint32_t)row * 128 + ((glA ^ ((uint32_t)row & 7u)) << 4);
        }
        const int rlB = ((lane >> 4) << 3) + (lane & 7);
        const uint32_t glB = (uint32_t)((lane >> 3) & 1);
        #pragma unroll
        for (int np = 0; np < 4; np++) {
            int row = wn * 64 + np * 16 + rlB;
            lbB[np] = (uint32_t)row * 128 + ((glB ^ ((uint32_t)row & 7u)) << 4);
        }
    }

    // ---------- prologue: one stage in flight ----------
    load_stage();

    // ---------- mainloop: 2-stage, SINGLE barrier per iteration ----------
    // top of iter i: wait(load(i)); sync (orders compute(i-1) reads before the
    // overwrite below); issue load(i+1) into slot (i+1)&1 (= slot last read by
    // compute(i-1)); compute(i). load(i+1) overlaps all of compute(i).
    for (int i = 0; i < iters; i++) {
        cp_wait<0>();
        __syncthreads();
        if (fi < iters) load_stage();

        const uint32_t aslot = sbase + (uint32_t)(i & 1) * STAGE_BYTES;
        const uint32_t bslot = aslot + A_BYTES;
        uint32_t aB[4], bB[4];
        #pragma unroll
        for (int mt = 0; mt < 4; mt++) aB[mt] = aslot + lbA[mt];
        #pragma unroll
        for (int np = 0; np < 4; np++) bB[np] = bslot + lbB[np];

        #pragma unroll
        for (int ks = 0; ks < 4; ks++) {
            const uint32_t x = (uint32_t)ks << 5;
            uint32_t af[4][4], bfp[4][4];
            #pragma unroll
            for (int mt = 0; mt < 4; mt++) ldsm4(af[mt], aB[mt] ^ x);
            #pragma unroll
            for (int np = 0; np < 4; np++) ldsm4(bfp[np], bB[np] ^ x);
            #pragma unroll
            for (int mt = 0; mt < 4; mt++)
                #pragma unroll
                for (int r = 0; r < 4; r++) af[mt][r] = cvt_tf32(af[mt][r]);
            #pragma unroll
            for (int np = 0; np < 4; np++)
                #pragma unroll
                for (int r = 0; r < 4; r++) bfp[np][r] = cvt_tf32(bfp[np][r]);
            #pragma unroll
            for (int mt = 0; mt < 4; mt++)
                #pragma unroll
                for (int nt = 0; nt < 8; nt++)
                    mma_tf32(acc[mt][nt], af[mt], &bfp[nt >> 1][(nt & 1) * 2]);
        }
    }

    // ---------- epilogue: direct float2 stores ----------
    const int ldo = ENCODE ? F_DIM : H_DIM;
    float* ob = gOut + (size_t)z * BS_DIM * ldo;
    #pragma unroll
    for (int mt = 0; mt < 4; mt++) {
        #pragma unroll
        for (int nt = 0; nt < 8; nt++) {
            int row = m0 + wm * 64 + mt * 16 + r8;
            int col = n0 + wn * 64 + nt * 8 + t * 2;
            float v0 = acc[mt][nt][0], v1 = acc[mt][nt][1];
            float v2 = acc[mt][nt][2], v3 = acc[mt][nt][3];
            if (ENCODE) {
                v0 = fmaxf(v0, 0.0f); v1 = fmaxf(v1, 0.0f);
                v2 = fmaxf(v2, 0.0f); v3 = fmaxf(v3, 0.0f);
            }
            *(float2*)&ob[(size_t)row * ldo + col]       = make_float2(v0, v1);
            *(float2*)&ob[(size_t)(row + 8) * ldo + col] = make_float2(v2, v3);
        }
    }
}

extern "C" void kernel_launch(void* const* d_in, const int* in_sizes, int n_in,
                              void* d_out, int out_size) {
    (void)in_sizes; (void)n_in; (void)out_size;
    const float* resid = (const float*)d_in[0];   // [L, B, S, H]
    const float* enc_w = (const float*)d_in[1];   // [L, F, H]
    const float* dec_w = (const float*)d_in[2];   // [L, L, H, F]
    float* out   = (float*)d_out;
    float* feats = out;                                   // [L, BS, F]
    float* recon = out + (size_t)L_DIM * BS_DIM * F_DIM;  // [L, BS, H]

    cudaFuncSetAttribute(clt_gemm<true>,  cudaFuncAttributeMaxDynamicSharedMemorySize, SMEM_BYTES);
    cudaFuncSetAttribute(clt_gemm<false>, cudaFuncAttributeMaxDynamicSharedMemorySize, SMEM_BYTES);

    dim3 grid_enc(BS_DIM / TM, F_DIM / TN, L_DIM);   // 16 x 4 x 16
    clt_gemm<true><<<grid_enc, NTHREADS, SMEM_BYTES>>>(resid, enc_w, feats);

    dim3 grid_dec(BS_DIM / TM, H_DIM / TN, L_DIM);   // 16 x 16 x 16
    clt_gemm<false><<<grid_dec, NTHREADS, SMEM_BYTES>>>(feats, dec_w, recon);
}

// round 17
// speedup vs baseline: 1.0762x; 1.0762x over previous
// CrossLayerTranscoder — tf32 mma.sync GEMM. R17 = R15 champion (128x128 CTA,
// 4 warps of 64x64, 2 CTAs/SM, 3-stage cp.async, XOR swizzle, ldmatrix x4
// fragment loads) + ks ping-pong: ldsm+cvt of ks+1 issued between the 32 MMAs
// of ks, giving each of the 2 warps/SMSP independent work at the dependency
// heads where they currently stall together. +64 frag regs (~220 total, fits
// 2 CTAs/SM). R16's 3-CTA reg cap (168) caused rematerialization — reverted.
//
// encode: feats[l] = relu(resid[l] @ enc_w[l]^T)            M=2048,N=512,K=2048
// decode: recon[t] = sum_{s<=t} feats[s] @ dec_w[s,t]^T     M=2048,N=2048,K=(t+1)*512

#include <cuda_runtime.h>
#include <cstdint>
#include <cstddef>

#define L_DIM 16
#define BS_DIM 2048
#define H_DIM 2048
#define F_DIM 512

#define TM 128
#define TN 128
#define TK 32
#define STAGES 3
#define NTHREADS 128

#define A_BYTES 16384                        // TM*TK*4
#define STAGE_BYTES 32768                    // A + B
#define SMEM_BYTES (STAGES * STAGE_BYTES)    // 96 KB (x2 CTAs = 192 KB)

__device__ __forceinline__ uint32_t smem_u32(const void* p) {
    uint32_t a;
    asm("{ .reg .u64 t; cvta.to.shared.u64 t, %1; cvt.u32.u64 %0, t; }" : "=r"(a) : "l"(p));
    return a;
}
__device__ __forceinline__ void cp_async16(uint32_t dst, const float* src) {
    asm volatile("cp.async.cg.shared.global [%0], [%1], 16;" :: "r"(dst), "l"(src));
}
__device__ __forceinline__ void cp_commit() { asm volatile("cp.async.commit_group;"); }
template <int N> __device__ __forceinline__ void cp_wait() {
    asm volatile("cp.async.wait_group %0;" :: "n"(N));
}
__device__ __forceinline__ void ldsm4(uint32_t* r, uint32_t addr) {
    asm volatile("ldmatrix.sync.aligned.m8n8.x4.shared.b16 {%0,%1,%2,%3}, [%4];"
                 : "=r"(r[0]), "=r"(r[1]), "=r"(r[2]), "=r"(r[3]) : "r"(addr));
}
__device__ __forceinline__ uint32_t cvt_tf32(uint32_t x) {
    uint32_t r; float f = __uint_as_float(x);
    asm("cvt.rna.tf32.f32 %0, %1;" : "=r"(r) : "f"(f));
    return r;
}
__device__ __forceinline__ void mma_tf32(float* c, const uint32_t* a, const uint32_t* b) {
    asm volatile(
        "mma.sync.aligned.m16n8k8.row.col.f32.tf32.tf32.f32 "
        "{%0,%1,%2,%3}, {%4,%5,%6,%7}, {%8,%9}, {%0,%1,%2,%3};"
        : "+f"(c[0]), "+f"(c[1]), "+f"(c[2]), "+f"(c[3])
        : "r"(a[0]), "r"(a[1]), "r"(a[2]), "r"(a[3]), "r"(b[0]), "r"(b[1]));
}

// SMEM tile layout (XOR swizzle): addr(row,k) = row*128 + ((k>>2 ^ (row&7))<<4)
// + (k&3)*4. ldmatrix bases fold the lane's k-group; ks XORs in as base^(ks<<5).

template <bool ENCODE>
__global__ __launch_bounds__(NTHREADS, 2)
void clt_gemm(const float* __restrict__ gA, const float* __restrict__ gB,
              float* __restrict__ gOut) {
    extern __shared__ float smem[];
    const uint32_t sbase = smem_u32(smem);
    const int tid  = threadIdx.x;
    const int lane = tid & 31;
    const int w    = tid >> 5;
    const int wm   = w & 1;        // 2 warps along M (64 rows)
    const int wn   = w >> 1;       // 2 warps along N (64 cols)
    const int r8   = lane >> 2;
    const int t    = lane & 3;
    const int m0   = blockIdx.x * TM;
    const int n0   = blockIdx.y * TN;
    const int z    = (int)gridDim.z - 1 - (int)blockIdx.z;   // heavy z first
    const int iters = ENCODE ? (H_DIM / TK) : ((z + 1) * (F_DIM / TK));
    const int LD   = ENCODE ? H_DIM : F_DIM;   // compile-time row pitch

    float acc[4][8][4];
    #pragma unroll
    for (int mt = 0; mt < 4; mt++)
        #pragma unroll
        for (int nt = 0; nt < 8; nt++)
            #pragma unroll
            for (int r = 0; r < 4; r++) acc[mt][nt][r] = 0.0f;

    // ---------- producer (coalesced, incremental; unchanged from R15) ----------
    const int tid8 = tid >> 3;
    const int cch  = tid & 7;
    const float* pA;
    const float* pB;
    if (ENCODE) {
        pA = gA + ((size_t)z * BS_DIM + m0 + tid8) * H_DIM + cch * 4;
        pB = gB + ((size_t)z * F_DIM + n0 + tid8) * H_DIM + cch * 4;
    } else {
        pA = gA + (size_t)(m0 + tid8) * F_DIM + cch * 4;               // feats[0]
        pB = gB + ((size_t)z * H_DIM + n0 + tid8) * F_DIM + cch * 4;   // dec_w[0][z]
    }
    const uint32_t dst0 = (uint32_t)tid8 * 128 + ((uint32_t)(cch ^ (tid8 & 7)) << 4);
    int fi = 0;
    auto load_stage = [&]() {
        const int slot = fi % STAGES;
        uint32_t dA = sbase + (uint32_t)slot * STAGE_BYTES + dst0;
        uint32_t dB = dA + A_BYTES;
        #pragma unroll
        for (int j = 0; j < 8; j++)
            cp_async16(dA + (uint32_t)j * 2048, pA + (size_t)j * 16 * LD);
        #pragma unroll
        for (int j = 0; j < 8; j++)
            cp_async16(dB + (uint32_t)j * 2048, pB + (size_t)j * 16 * LD);
        cp_commit();
        if (ENCODE) { pA += TK; pB += TK; }
        else {
            bool roll = (fi & 15) == 15;   // advance source layer s
            pA += roll ? ((size_t)BS_DIM * F_DIM - 15 * TK) : TK;
            pB += roll ? ((size_t)L_DIM * H_DIM * F_DIM - 15 * TK) : TK;
        }
        fi++;
    };

    // ---------- per-lane ldmatrix base offsets (bytes within tile) ----------
    uint32_t lbA[4], lbB[4];
    {
        const int rlA = lane & 15;
        const uint32_t glA = (uint32_t)(lane >> 4);
        #pragma unroll
        for (int mt = 0; mt < 4; mt++) {
            int row = wm * 64 + mt * 16 + rlA;
            lbA[mt] = (uint32_t)row * 128 + ((glA ^ ((uint32_t)row & 7u)) << 4);
        }
        const int rlB = ((lane >> 4) << 3) + (lane & 7);
        const uint32_t glB = (uint32_t)((lane >> 3) & 1);
        #pragma unroll
        for (int np = 0; np < 4; np++) {
            int row = wn * 64 + np * 16 + rlB;
            lbB[np] = (uint32_t)row * 128 + ((glB ^ ((uint32_t)row & 7u)) << 4);
        }
    }

    // ---------- prologue ----------
    load_stage();
    load_stage();

    // ---------- mainloop: single barrier/iter, ks ping-pong fragments ----------
    uint32_t af[2][4][4], bfp[2][4][4];
    for (int i = 0; i < iters; i++) {
        cp_wait<STAGES - 2>();
        __syncthreads();
        if (fi < iters) load_stage();

        const uint32_t aslot = sbase + (uint32_t)(i % STAGES) * STAGE_BYTES;
        const uint32_t bslot = aslot + A_BYTES;
        uint32_t aB[4], bB[4];
        #pragma unroll
        for (int mt = 0; mt < 4; mt++) aB[mt] = aslot + lbA[mt];
        #pragma unroll
        for (int np = 0; np < 4; np++) bB[np] = bslot + lbB[np];

        // fragment fetch+convert for k-step ks into buffer cb
        auto fetch = [&](int ks, int cb) {
            const uint32_t x = (uint32_t)ks << 5;
            #pragma unroll
            for (int mt = 0; mt < 4; mt++) ldsm4(af[cb][mt], aB[mt] ^ x);
            #pragma unroll
            for (int np = 0; np < 4; np++) ldsm4(bfp[cb][np], bB[np] ^ x);
            #pragma unroll
            for (int mt = 0; mt < 4; mt++)
                #pragma unroll
                for (int r = 0; r < 4; r++) af[cb][mt][r] = cvt_tf32(af[cb][mt][r]);
            #pragma unroll
            for (int np = 0; np < 4; np++)
                #pragma unroll
                for (int r = 0; r < 4; r++) bfp[cb][np][r] = cvt_tf32(bfp[cb][np][r]);
        };

        fetch(0, 0);
        #pragma unroll
        for (int ks = 0; ks < 4; ks++) {
            const int cb = ks & 1;
            if (ks < 3) fetch(ks + 1, cb ^ 1);   // shadowed by the 32 MMAs below
            #pragma unroll
            for (int mt = 0; mt < 4; mt++)
                #pragma unroll
                for (int nt = 0; nt < 8; nt++)
                    mma_tf32(acc[mt][nt], af[cb][mt], &bfp[cb][nt >> 1][(nt & 1) * 2]);
        }
    }

    // ---------- epilogue: direct float2 stores ----------
    const int ldo = ENCODE ? F_DIM : H_DIM;
    float* ob = gOut + (size_t)z * BS_DIM * ldo;
    #pragma unroll
    for (int mt = 0; mt < 4; mt++) {
        #pragma unroll
        for (int nt = 0; nt < 8; nt++) {
            int row = m0 + wm * 64 + mt * 16 + r8;
            int col = n0 + wn * 64 + nt * 8 + t * 2;
            float v0 = acc[mt][nt][0], v1 = acc[mt][nt][1];
            float v2 = acc[mt][nt][2], v3 = acc[mt][nt][3];
            if (ENCODE) {
                v0 = fmaxf(v0, 0.0f); v1 = fmaxf(v1, 0.0f);
                v2 = fmaxf(v2, 0.0f); v3 = fmaxf(v3, 0.0f);
            }
            *(float2*)&ob[(size_t)row * ldo + col]       = make_float2(v0, v1);
            *(float2*)&ob[(size_t)(row + 8) * ldo + col] = make_float2(v2, v3);
        }
    }
}

extern "C" void kernel_launch(void* const* d_in, const int* in_sizes, int n_in,
                              void* d_out, int out_size) {
    (void)in_sizes; (void)n_in; (void)out_size;
    const float* resid = (const float*)d_in[0];   // [L, B, S, H]
    const float* enc_w = (const float*)d_in[1];   // [L, F, H]
    const float* dec_w = (const float*)d_in[2];   // [L, L, H, F]
    float* out   = (float*)d_out;
    float* feats = out;                                   // [L, BS, F]
    float* recon = out + (size_t)L_DIM * BS_DIM * F_DIM;  // [L, BS, H]

    cudaFuncSetAttribute(clt_gemm<true>,  cudaFuncAttributeMaxDynamicSharedMemorySize, SMEM_BYTES);
    cudaFuncSetAttribute(clt_gemm<false>, cudaFuncAttributeMaxDynamicSharedMemorySize, SMEM_BYTES);

    dim3 grid_enc(BS_DIM / TM, F_DIM / TN, L_DIM);   // 16 x 4 x 16
    clt_gemm<true><<<grid_enc, NTHREADS, SMEM_BYTES>>>(resid, enc_w, feats);

    dim3 grid_dec(BS_DIM / TM, H_DIM / TN, L_DIM);   // 16 x 16 x 16
    clt_gemm<false><<<grid_dec, NTHREADS, SMEM_BYTES>>>(feats, dec_w, recon);
}